// round 5
// baseline (speedup 1.0000x reference)
#include <cuda_runtime.h>
#include <cuda_bf16.h>

#define NB 64
#define SL 1024
#define NT 48
#define DM 512
#define TD 50
#define FULL 0xffffffffu

static __device__ float g_tagvec[(size_t)NB * SL * NT];

__device__ __forceinline__ float wmaxr(float v) {
#pragma unroll
    for (int o = 16; o > 0; o >>= 1) v = fmaxf(v, __shfl_xor_sync(FULL, v, o));
    return v;
}
__device__ __forceinline__ float wsumr(float v) {
#pragma unroll
    for (int o = 16; o > 0; o >>= 1) v += __shfl_xor_sync(FULL, v, o);
    return v;
}

// ---------------------------------------------------------------------------
// GEMM: g_tagvec[m][t] = (sum_k feat[m][k] * W[t][k]) / sqrt(512)
// M = 65536, N = 48, K = 512. BM=128, BN=48, BK=16. 128 threads, 8x6/thread.
// ---------------------------------------------------------------------------
__global__ __launch_bounds__(128) void gemm_kernel(const float* __restrict__ A,
                                                   const float* __restrict__ W) {
    __shared__ __align__(16) float As[16][128];
    __shared__ float Bs[16][NT];
    const int tid = threadIdx.x;
    const int tx = tid & 7;   // n blocking (8 groups of 6)
    const int ty = tid >> 3;  // m blocking (16 groups of 8)
    const int rowBase = blockIdx.x * 128;

    float acc[8][6];
#pragma unroll
    for (int i = 0; i < 8; i++)
#pragma unroll
        for (int c = 0; c < 6; c++) acc[i][c] = 0.f;

    for (int k0 = 0; k0 < DM; k0 += 16) {
#pragma unroll
        for (int r = 0; r < 4; r++) {
            int f4i = tid + r * 128;      // 0..511
            int row = f4i >> 2;           // 0..127
            int kq = (f4i & 3) << 2;      // 0,4,8,12
            float4 v = *reinterpret_cast<const float4*>(
                A + (size_t)(rowBase + row) * DM + k0 + kq);
            As[kq + 0][row] = v.x;
            As[kq + 1][row] = v.y;
            As[kq + 2][row] = v.z;
            As[kq + 3][row] = v.w;
        }
#pragma unroll
        for (int r = 0; r < 6; r++) {
            int e = tid + r * 128;        // 0..767
            int kk = e & 15;
            int n = e >> 4;               // 0..47
            Bs[kk][n] = W[n * DM + k0 + kk];
        }
        __syncthreads();
#pragma unroll
        for (int kk = 0; kk < 16; kk++) {
            float a[8], bb[6];
            const float4* a4 = reinterpret_cast<const float4*>(&As[kk][ty * 8]);
            float4 x0 = a4[0], x1 = a4[1];
            a[0] = x0.x; a[1] = x0.y; a[2] = x0.z; a[3] = x0.w;
            a[4] = x1.x; a[5] = x1.y; a[6] = x1.z; a[7] = x1.w;
#pragma unroll
            for (int c = 0; c < 6; c++) bb[c] = Bs[kk][tx * 6 + c];
#pragma unroll
            for (int i = 0; i < 8; i++)
#pragma unroll
                for (int c = 0; c < 6; c++) acc[i][c] = fmaf(a[i], bb[c], acc[i][c]);
        }
        __syncthreads();
    }
    const float scale = 0.04419417382415922f;  // 1/sqrt(512)
#pragma unroll
    for (int i = 0; i < 8; i++) {
        size_t row = rowBase + ty * 8 + i;
#pragma unroll
        for (int c = 0; c < 6; c++)
            g_tagvec[row * NT + tx * 6 + c] = acc[i][c] * scale;
    }
}

// ---------------------------------------------------------------------------
// Scan: blocks 0..63 forward (loss), blocks 64..127 viterbi (path).
// blockDim = 64, dynamic smem = 48KB (viterbi stage indices).
// ---------------------------------------------------------------------------
__global__ void scan_kernel(const int* __restrict__ y, const float* __restrict__ trans,
                            float* __restrict__ out, int out_size) {
    extern __shared__ unsigned char idxS[];  // [SL * NT] bytes (viterbi only)

    if (blockIdx.x < NB) {
        // ===================== FORWARD: one warp per batch =====================
        if (threadIdx.x >= 32) return;
        const int b = blockIdx.x;
        const int lane = threadIdx.x;
        const float* tv = g_tagvec + (size_t)b * SL * NT;
        const bool hi = lane < 16;
        const int lane2 = hi ? (32 + lane) : 47;  // clamped second-state index

        // Columns of exp(T): E0 for j0=lane, E1 for j1=32+lane (lane<16).
        float E0[48], E1[48];
#pragma unroll
        for (int i = 0; i < 48; i++) {
            E0[i] = __expf(trans[i * TD + lane]);
            E1[i] = hi ? __expf(trans[i * TD + lane2]) : 0.f;
        }
        float prev0 = trans[48 * TD + lane];                     // start[j0]
        float prev1 = hi ? trans[48 * TD + lane2] : -1e30f;      // start[j1]
        float m = wmaxr(fmaxf(prev0, prev1));

        float e0 = tv[lane];
        float e1 = hi ? tv[lane2] : 0.f;

        for (int s = 0; s < SL - 1; s++) {
            float a0 = prev0 + e0;
            float a1 = prev1 + e1;
            float p0 = __expf(a0 - m);  // delayed max: exact, bounded exponent
            float p1 = __expf(a1 - m);
            float mn = wmaxr(fmaxf(a0, a1));  // for next step (off critical path)
            float aA[4] = {0.f, 0.f, 0.f, 0.f};
            float aB[4] = {0.f, 0.f, 0.f, 0.f};
#pragma unroll
            for (int i = 0; i < 32; i++) {
                float q = __shfl_sync(FULL, p0, i);
                aA[i & 3] = fmaf(q, E0[i], aA[i & 3]);
                aB[i & 3] = fmaf(q, E1[i], aB[i & 3]);
            }
#pragma unroll
            for (int i = 0; i < 16; i++) {
                float q = __shfl_sync(FULL, p1, i);
                aA[i & 3] = fmaf(q, E0[32 + i], aA[i & 3]);
                aB[i & 3] = fmaf(q, E1[32 + i], aB[i & 3]);
            }
            float s0 = (aA[0] + aA[1]) + (aA[2] + aA[3]);
            float s1 = (aB[0] + aB[1]) + (aB[2] + aB[3]);
            prev0 = m + __logf(fmaxf(s0, 1e-37f));
            prev1 = hi ? (m + __logf(fmaxf(s1, 1e-37f))) : -1e30f;
            m = mn;
            e0 = tv[(s + 1) * NT + lane];
            e1 = hi ? tv[(s + 1) * NT + lane2] : 0.f;
        }
        // Final step: bm_next = 0 -> logZ = lse_i(prev_i + e_i) + lse_j(end_j)
        float a0 = prev0 + e0;
        float a1 = prev1 + e1;
        float mm = wmaxr(fmaxf(a0, a1));
        float ss = wsumr(__expf(a0 - mm) + __expf(a1 - mm));
        float C = mm + __logf(ss);
        float x0 = trans[lane * TD + 49];                        // end[j0]
        float x1 = hi ? trans[lane2 * TD + 49] : -1e30f;        // end[j1]
        float mm2 = wmaxr(fmaxf(x0, x1));
        float s2 = wsumr(__expf(x0 - mm2) + __expf(x1 - mm2));
        float logZ = C + mm2 + __logf(s2);

        // Path score of y
        float accs = 0.f;
        const int* yb = y + b * SL;
        for (int it = 0; it < SL / 32; it++) {
            int s = it * 32 + lane;
            int ys = yb[s];
            accs += tv[s * NT + ys];
            if (s < SL - 1) accs += trans[ys * TD + yb[s + 1]];
        }
        float score = wsumr(accs);
        if (lane == 0) {
            score += trans[48 * TD + yb[0]] + trans[yb[SL - 1] * TD + 49];
            if (out_size >= NB + NB * SL) out[b] = logZ - score;
        }
    } else {
        // ===================== VITERBI: one block per batch =====================
        __shared__ float bestA[48], bestB[48];
        const int b = blockIdx.x - NB;
        const float* tv = g_tagvec + (size_t)b * SL * NT;
        const int t = threadIdx.x;
        const bool act = t < 48;

        float Tc[48];
        if (act) {
#pragma unroll
            for (int i = 0; i < 48; i++) Tc[i] = trans[i * TD + t];
            bestA[t] = trans[48 * TD + t] + tv[t];  // stage 0: start[j] + e0[j]
        }
        __syncthreads();

        float* cur = bestA;
        float* nxt = bestB;
        for (int s = 1; s < SL; s++) {
            if (act) {
                float e = tv[s * NT + t];
                float v[4] = {-3e38f, -3e38f, -3e38f, -3e38f};
                int id[4] = {0, 1, 2, 3};
#pragma unroll
                for (int i = 0; i < 48; i++) {
                    // exact ref rounding: (best_prev + T) + e, then max
                    float cand = (cur[i] + Tc[i]) + e;
                    int c = i & 3;
                    bool g = cand > v[c];          // strict > keeps first max
                    v[c] = g ? cand : v[c];
                    id[c] = g ? i : id[c];
                }
                float mv = v[0]; int mi = id[0];
                if (v[1] > mv || (v[1] == mv && id[1] < mi)) { mv = v[1]; mi = id[1]; }
                if (v[2] > mv || (v[2] == mv && id[2] < mi)) { mv = v[2]; mi = id[2]; }
                if (v[3] > mv || (v[3] == mv && id[3] < mi)) { mv = v[3]; mi = id[3]; }
                nxt[t] = mv;  // e already included (matches reference)
                idxS[s * NT + t] = (unsigned char)mi;
            }
            __syncthreads();
            float* tmp = cur; cur = nxt; nxt = tmp;
        }

        if (t == 0) {
            float bv = -3e38f;
            int now = 0;
#pragma unroll
            for (int j = 0; j < 48; j++) {
                float f = cur[j] + trans[j * TD + 49];
                if (f > bv) { bv = f; now = j; }
            }
            int off = (out_size >= NB + NB * SL) ? NB : 0;
            float* po = out + off + (size_t)b * SL;
            po[SL - 1] = (float)now;
            for (int s = SL - 1; s >= 1; s--) {
                now = idxS[s * NT + now];
                po[s - 1] = (float)now;
            }
        }
    }
}

extern "C" void kernel_launch(void* const* d_in, const int* in_sizes, int n_in,
                              void* d_out, int out_size) {
    const float* feat  = (const float*)d_in[0];   // [64,1024,512] f32
    const int*   y     = (const int*)d_in[1];     // [64,1024] i32
    const float* W     = (const float*)d_in[3];   // [48,512] f32
    const float* trans = (const float*)d_in[4];   // [50,50] f32
    float* out = (float*)d_out;

    // Opt-in for 48KB dynamic + 384B static shared on scan_kernel.
    // Deterministic, not a stream op (legal during graph capture, adds no nodes).
    cudaFuncSetAttribute(scan_kernel, cudaFuncAttributeMaxDynamicSharedMemorySize,
                         SL * NT + 1024);

    gemm_kernel<<<512, 128>>>(feat, W);
    scan_kernel<<<2 * NB, 64, SL * NT>>>(y, trans, out, out_size);
}

// round 6
// speedup vs baseline: 1.2192x; 1.2192x over previous
#include <cuda_runtime.h>
#include <cuda_bf16.h>

#define NB 64
#define SL 1024
#define NT 48
#define DM 512
#define TD 50
#define FULL 0xffffffffu

static __device__ float g_tagvec[(size_t)NB * SL * NT];

__device__ __forceinline__ float wmaxr(float v) {
#pragma unroll
    for (int o = 16; o > 0; o >>= 1) v = fmaxf(v, __shfl_xor_sync(FULL, v, o));
    return v;
}
__device__ __forceinline__ float wsumr(float v) {
#pragma unroll
    for (int o = 16; o > 0; o >>= 1) v += __shfl_xor_sync(FULL, v, o);
    return v;
}

// ---------------------------------------------------------------------------
// GEMM: g_tagvec[m][t] = (sum_k feat[m][k] * W[t][k]) / sqrt(512)
// M = 65536, N = 48, K = 512. BM=128, BN=48, BK=16. 128 threads, 8x6/thread.
// ---------------------------------------------------------------------------
__global__ __launch_bounds__(128) void gemm_kernel(const float* __restrict__ A,
                                                   const float* __restrict__ W) {
    __shared__ __align__(16) float As[16][128];
    __shared__ float Bs[16][NT];
    const int tid = threadIdx.x;
    const int tx = tid & 7;   // n blocking (8 groups of 6)
    const int ty = tid >> 3;  // m blocking (16 groups of 8)
    const int rowBase = blockIdx.x * 128;

    float acc[8][6];
#pragma unroll
    for (int i = 0; i < 8; i++)
#pragma unroll
        for (int c = 0; c < 6; c++) acc[i][c] = 0.f;

    for (int k0 = 0; k0 < DM; k0 += 16) {
#pragma unroll
        for (int r = 0; r < 4; r++) {
            int f4i = tid + r * 128;      // 0..511
            int row = f4i >> 2;           // 0..127
            int kq = (f4i & 3) << 2;      // 0,4,8,12
            float4 v = *reinterpret_cast<const float4*>(
                A + (size_t)(rowBase + row) * DM + k0 + kq);
            As[kq + 0][row] = v.x;
            As[kq + 1][row] = v.y;
            As[kq + 2][row] = v.z;
            As[kq + 3][row] = v.w;
        }
#pragma unroll
        for (int r = 0; r < 6; r++) {
            int e = tid + r * 128;        // 0..767
            int kk = e & 15;
            int n = e >> 4;               // 0..47
            Bs[kk][n] = W[n * DM + k0 + kk];
        }
        __syncthreads();
#pragma unroll
        for (int kk = 0; kk < 16; kk++) {
            float a[8], bb[6];
            const float4* a4 = reinterpret_cast<const float4*>(&As[kk][ty * 8]);
            float4 x0 = a4[0], x1 = a4[1];
            a[0] = x0.x; a[1] = x0.y; a[2] = x0.z; a[3] = x0.w;
            a[4] = x1.x; a[5] = x1.y; a[6] = x1.z; a[7] = x1.w;
#pragma unroll
            for (int c = 0; c < 6; c++) bb[c] = Bs[kk][tx * 6 + c];
#pragma unroll
            for (int i = 0; i < 8; i++)
#pragma unroll
                for (int c = 0; c < 6; c++) acc[i][c] = fmaf(a[i], bb[c], acc[i][c]);
        }
        __syncthreads();
    }
    const float scale = 0.04419417382415922f;  // 1/sqrt(512)
#pragma unroll
    for (int i = 0; i < 8; i++) {
        size_t row = rowBase + ty * 8 + i;
#pragma unroll
        for (int c = 0; c < 6; c++)
            g_tagvec[row * NT + tx * 6 + c] = acc[i][c] * scale;
    }
}

// ---------------------------------------------------------------------------
// Scan: blocks 0..63 forward (loss), blocks 64..127 viterbi (path).
// blockDim = 128. Viterbi: 2-way i-split (threads 0-47 and 64-111), e prefetch.
// ---------------------------------------------------------------------------
__global__ void scan_kernel(const int* __restrict__ y, const float* __restrict__ trans,
                            float* __restrict__ out, int out_size) {
    extern __shared__ unsigned char idxS[];  // [SL * NT] bytes (viterbi only)

    if (blockIdx.x < NB) {
        // ===================== FORWARD: one warp per batch =====================
        if (threadIdx.x >= 32) return;
        const int b = blockIdx.x;
        const int lane = threadIdx.x;
        const float* tv = g_tagvec + (size_t)b * SL * NT;
        const bool hi = lane < 16;
        const int lane2 = hi ? (32 + lane) : 47;

        float E0[48], E1[48];
#pragma unroll
        for (int i = 0; i < 48; i++) {
            E0[i] = __expf(trans[i * TD + lane]);
            E1[i] = hi ? __expf(trans[i * TD + lane2]) : 0.f;
        }
        float prev0 = trans[48 * TD + lane];
        float prev1 = hi ? trans[48 * TD + lane2] : -1e30f;
        float m = wmaxr(fmaxf(prev0, prev1));

        float e0 = tv[lane];
        float e1 = hi ? tv[lane2] : 0.f;

        for (int s = 0; s < SL - 1; s++) {
            float a0 = prev0 + e0;
            float a1 = prev1 + e1;
            float p0 = __expf(a0 - m);  // delayed max: exact, bounded exponent
            float p1 = __expf(a1 - m);
            float mn = wmaxr(fmaxf(a0, a1));
            float aA[4] = {0.f, 0.f, 0.f, 0.f};
            float aB[4] = {0.f, 0.f, 0.f, 0.f};
#pragma unroll
            for (int i = 0; i < 32; i++) {
                float q = __shfl_sync(FULL, p0, i);
                aA[i & 3] = fmaf(q, E0[i], aA[i & 3]);
                aB[i & 3] = fmaf(q, E1[i], aB[i & 3]);
            }
#pragma unroll
            for (int i = 0; i < 16; i++) {
                float q = __shfl_sync(FULL, p1, i);
                aA[i & 3] = fmaf(q, E0[32 + i], aA[i & 3]);
                aB[i & 3] = fmaf(q, E1[32 + i], aB[i & 3]);
            }
            float s0 = (aA[0] + aA[1]) + (aA[2] + aA[3]);
            float s1 = (aB[0] + aB[1]) + (aB[2] + aB[3]);
            prev0 = m + __logf(fmaxf(s0, 1e-37f));
            prev1 = hi ? (m + __logf(fmaxf(s1, 1e-37f))) : -1e30f;
            m = mn;
            e0 = tv[(s + 1) * NT + lane];
            e1 = hi ? tv[(s + 1) * NT + lane2] : 0.f;
        }
        float a0 = prev0 + e0;
        float a1 = prev1 + e1;
        float mm = wmaxr(fmaxf(a0, a1));
        float ss = wsumr(__expf(a0 - mm) + __expf(a1 - mm));
        float C = mm + __logf(ss);
        float x0 = trans[lane * TD + 49];
        float x1 = hi ? trans[lane2 * TD + 49] : -1e30f;
        float mm2 = wmaxr(fmaxf(x0, x1));
        float s2 = wsumr(__expf(x0 - mm2) + __expf(x1 - mm2));
        float logZ = C + mm2 + __logf(s2);

        float accs = 0.f;
        const int* yb = y + b * SL;
        for (int it = 0; it < SL / 32; it++) {
            int s = it * 32 + lane;
            int ys = yb[s];
            accs += tv[s * NT + ys];
            if (s < SL - 1) accs += trans[ys * TD + yb[s + 1]];
        }
        float score = wsumr(accs);
        if (lane == 0) {
            score += trans[48 * TD + yb[0]] + trans[yb[SL - 1] * TD + 49];
            if (out_size >= NB + NB * SL) out[b] = logZ - score;
        }
    } else {
        // ============ VITERBI: one block per batch, 2-way i-split ============
        __shared__ float bestA[48], bestB[48];
        __shared__ float pv1[48];
        __shared__ int pi1[48];
        const int b = blockIdx.x - NB;
        const float* tv = g_tagvec + (size_t)b * SL * NT;
        const int t = threadIdx.x;
        const int half = t >> 6;        // 0: threads 0-63, 1: threads 64-127
        const int j = t & 63;
        const bool act = j < 48;
        const int i0 = half * 24;

        float Tc[24];
        if (act) {
#pragma unroll
            for (int r = 0; r < 24; r++) Tc[r] = trans[(i0 + r) * TD + j];
            if (half == 0) bestA[j] = trans[48 * TD + j] + tv[j];  // start + e0
        }
        __syncthreads();

        float en = act ? tv[NT + j] : 0.f;  // prefetched e for s=1
        float* cur = bestA;
        float* nxt = bestB;
        for (int s = 1; s < SL; s++) {
            float mv = -3e38f;
            int mi = i0;
            if (act) {
                float e = en;
                int sn = (s + 1 < SL) ? (s + 1) : s;
                en = tv[sn * NT + j];  // prefetch next step's emission

                float v[4] = {-3e38f, -3e38f, -3e38f, -3e38f};
                int id[4] = {i0, i0 + 1, i0 + 2, i0 + 3};
#pragma unroll
                for (int r = 0; r < 24; r++) {
                    // reference-exact rounding: (best_prev + T) + e, then max
                    float cand = (cur[i0 + r] + Tc[r]) + e;
                    int c = r & 3;
                    bool g = cand > v[c];  // strict > keeps first index
                    v[c] = g ? cand : v[c];
                    id[c] = g ? (i0 + r) : id[c];
                }
                mv = v[0]; mi = id[0];
                if (v[1] > mv || (v[1] == mv && id[1] < mi)) { mv = v[1]; mi = id[1]; }
                if (v[2] > mv || (v[2] == mv && id[2] < mi)) { mv = v[2]; mi = id[2]; }
                if (v[3] > mv || (v[3] == mv && id[3] < mi)) { mv = v[3]; mi = id[3]; }
                if (half == 1) { pv1[j] = mv; pi1[j] = mi; }
            }
            __syncthreads();
            if (act && half == 0) {
                float v1 = pv1[j];
                if (v1 > mv) { mv = v1; mi = pi1[j]; }  // tie -> half0 (lower i)
                nxt[j] = mv;                             // e already included
                idxS[s * NT + j] = (unsigned char)mi;
            }
            __syncthreads();
            float* tmp = cur; cur = nxt; nxt = tmp;
        }

        if (t == 0) {
            float bv = -3e38f;
            int now = 0;
#pragma unroll
            for (int jj = 0; jj < 48; jj++) {
                float f = cur[jj] + trans[jj * TD + 49];
                if (f > bv) { bv = f; now = jj; }
            }
            int off = (out_size >= NB + NB * SL) ? NB : 0;
            float* po = out + off + (size_t)b * SL;
            po[SL - 1] = (float)now;
            for (int s = SL - 1; s >= 1; s--) {
                now = idxS[s * NT + now];
                po[s - 1] = (float)now;
            }
        }
    }
}

extern "C" void kernel_launch(void* const* d_in, const int* in_sizes, int n_in,
                              void* d_out, int out_size) {
    const float* feat  = (const float*)d_in[0];   // [64,1024,512] f32
    const int*   y     = (const int*)d_in[1];     // [64,1024] i32
    const float* W     = (const float*)d_in[3];   // [48,512] f32
    const float* trans = (const float*)d_in[4];   // [50,50] f32
    float* out = (float*)d_out;

    // Opt-in for 48KB dynamic shared on scan_kernel (deterministic, capture-legal).
    cudaFuncSetAttribute(scan_kernel, cudaFuncAttributeMaxDynamicSharedMemorySize,
                         SL * NT + 1024);

    gemm_kernel<<<512, 128>>>(feat, W);
    scan_kernel<<<2 * NB, 128, SL * NT>>>(y, trans, out, out_size);
}

// round 7
// speedup vs baseline: 1.2207x; 1.0013x over previous
#include <cuda_runtime.h>
#include <cuda_bf16.h>

#define NB 64
#define SL 1024
#define NT 48
#define DM 512
#define TD 50
#define FULL 0xffffffffu

static __device__ float g_tagvec[(size_t)NB * SL * NT];

__device__ __forceinline__ float wmaxr(float v) {
#pragma unroll
    for (int o = 16; o > 0; o >>= 1) v = fmaxf(v, __shfl_xor_sync(FULL, v, o));
    return v;
}
__device__ __forceinline__ float wsumr(float v) {
#pragma unroll
    for (int o = 16; o > 0; o >>= 1) v += __shfl_xor_sync(FULL, v, o);
    return v;
}
__device__ __forceinline__ void barrier64() {
    asm volatile("bar.sync 1, 64;" ::: "memory");
}

// ---------------------------------------------------------------------------
// GEMM: g_tagvec[m][t] = (sum_k feat[m][k] * W[t][k]) / sqrt(512)
// ---------------------------------------------------------------------------
__global__ __launch_bounds__(128) void gemm_kernel(const float* __restrict__ A,
                                                   const float* __restrict__ W) {
    __shared__ __align__(16) float As[16][128];
    __shared__ float Bs[16][NT];
    const int tid = threadIdx.x;
    const int tx = tid & 7;
    const int ty = tid >> 3;
    const int rowBase = blockIdx.x * 128;

    float acc[8][6];
#pragma unroll
    for (int i = 0; i < 8; i++)
#pragma unroll
        for (int c = 0; c < 6; c++) acc[i][c] = 0.f;

    for (int k0 = 0; k0 < DM; k0 += 16) {
#pragma unroll
        for (int r = 0; r < 4; r++) {
            int f4i = tid + r * 128;
            int row = f4i >> 2;
            int kq = (f4i & 3) << 2;
            float4 v = *reinterpret_cast<const float4*>(
                A + (size_t)(rowBase + row) * DM + k0 + kq);
            As[kq + 0][row] = v.x;
            As[kq + 1][row] = v.y;
            As[kq + 2][row] = v.z;
            As[kq + 3][row] = v.w;
        }
#pragma unroll
        for (int r = 0; r < 6; r++) {
            int e = tid + r * 128;
            int kk = e & 15;
            int n = e >> 4;
            Bs[kk][n] = W[n * DM + k0 + kk];
        }
        __syncthreads();
#pragma unroll
        for (int kk = 0; kk < 16; kk++) {
            float a[8], bb[6];
            const float4* a4 = reinterpret_cast<const float4*>(&As[kk][ty * 8]);
            float4 x0 = a4[0], x1 = a4[1];
            a[0] = x0.x; a[1] = x0.y; a[2] = x0.z; a[3] = x0.w;
            a[4] = x1.x; a[5] = x1.y; a[6] = x1.z; a[7] = x1.w;
#pragma unroll
            for (int c = 0; c < 6; c++) bb[c] = Bs[kk][tx * 6 + c];
#pragma unroll
            for (int i = 0; i < 8; i++)
#pragma unroll
                for (int c = 0; c < 6; c++) acc[i][c] = fmaf(a[i], bb[c], acc[i][c]);
        }
        __syncthreads();
    }
    const float scale = 0.04419417382415922f;  // 1/sqrt(512)
#pragma unroll
    for (int i = 0; i < 8; i++) {
        size_t row = rowBase + ty * 8 + i;
#pragma unroll
        for (int c = 0; c < 6; c++)
            g_tagvec[row * NT + tx * 6 + c] = acc[i][c] * scale;
    }
}

// ---------------------------------------------------------------------------
// Scan: blocks 0..63 forward (loss), blocks 64..127 viterbi (path).
// Forward: 64 threads, thread-per-state, p broadcast via double-buffered smem.
// ---------------------------------------------------------------------------
__global__ void scan_kernel(const int* __restrict__ y, const float* __restrict__ trans,
                            float* __restrict__ out, int out_size) {
    extern __shared__ unsigned char idxS[];  // [SL * NT] bytes (viterbi only)

    if (blockIdx.x < NB) {
        // ============ FORWARD: 2 warps per batch, thread j = state j ============
        if (threadIdx.x >= 64) return;
        __shared__ __align__(16) float sp[2][48];
        __shared__ float smax[2][2];
        const int b = blockIdx.x;
        const int t = threadIdx.x;
        const int wid = t >> 5;
        const int lane = t & 31;
        const bool act = t < NT;
        const float* tv = g_tagvec + (size_t)b * SL * NT;

        // E column j: E[i] = exp(T[i][j])
        float E[48];
        if (act) {
#pragma unroll
            for (int i = 0; i < 48; i++) E[i] = __expf(trans[i * TD + t]);
        }
        float prev = act ? trans[48 * TD + t] : -1e30f;  // start[j]
        float e = act ? tv[t] : 0.f;
        // m0 = max over states of prev
        {
            float wm = wmaxr(prev);
            if (lane == 0) smax[0][wid] = wm;
        }
        barrier64();
        float m = fmaxf(smax[0][0], smax[0][1]);

        int buf = 0;
        for (int s = 0; s < SL - 1; s++) {
            float a = prev + e;
            float p = __expf(a - m);     // delayed max: exact, bounded exponent
            float wm = wmaxr(a);         // for next step's m
            if (lane == 0) smax[buf][wid] = wm;
            if (act) sp[buf][t] = p;
            barrier64();
            float mn = fmaxf(smax[buf][0], smax[buf][1]);
            // prefetch next emission (hides L2 latency behind GEMV)
            float en = act ? tv[(s + 1) * NT + t] : 0.f;
            // GEMV: new_j = sum_i p_i * E[i][j], 4-bank order matches prior rounds
            float acc0 = 0.f, acc1 = 0.f, acc2 = 0.f, acc3 = 0.f;
            const float4* p4 = reinterpret_cast<const float4*>(sp[buf]);
#pragma unroll
            for (int q = 0; q < 12; q++) {
                float4 v = p4[q];
                acc0 = fmaf(v.x, E[4 * q + 0], acc0);
                acc1 = fmaf(v.y, E[4 * q + 1], acc1);
                acc2 = fmaf(v.z, E[4 * q + 2], acc2);
                acc3 = fmaf(v.w, E[4 * q + 3], acc3);
            }
            float s0 = (acc0 + acc1) + (acc2 + acc3);
            prev = act ? (m + __logf(fmaxf(s0, 1e-37f))) : -1e30f;
            m = mn;
            e = en;
            buf ^= 1;
        }
        // Final step: logZ = lse_j(prev_j + e_j) + lse_j(end_j)
        float a = prev + e;
        {
            float wm = wmaxr(a);
            if (lane == 0) smax[0][wid] = wm;
        }
        barrier64();
        float mm = fmaxf(smax[0][0], smax[0][1]);
        float ws = wsumr(__expf(a - mm));
        if (lane == 0) sp[0][wid] = ws;
        barrier64();
        float C = mm + __logf(sp[0][0] + sp[0][1]);

        float x = act ? trans[t * TD + 49] : -1e30f;  // end[j]
        {
            float wm = wmaxr(x);
            if (lane == 0) smax[1][wid] = wm;
        }
        barrier64();
        float mm2 = fmaxf(smax[1][0], smax[1][1]);
        float ws2 = wsumr(__expf(x - mm2));
        if (lane == 0) sp[1][wid] = ws2;
        barrier64();
        float logZ = C + mm2 + __logf(sp[1][0] + sp[1][1]);

        // Path score of y (warp 0 only)
        if (wid == 0) {
            float accs = 0.f;
            const int* yb = y + b * SL;
            for (int it = 0; it < SL / 32; it++) {
                int s = it * 32 + lane;
                int ys = yb[s];
                accs += tv[s * NT + ys];
                if (s < SL - 1) accs += trans[ys * TD + yb[s + 1]];
            }
            float score = wsumr(accs);
            if (lane == 0) {
                score += trans[48 * TD + yb[0]] + trans[yb[SL - 1] * TD + 49];
                if (out_size >= NB + NB * SL) out[b] = logZ - score;
            }
        }
    } else {
        // ============ VITERBI: one block per batch, 2-way i-split ============
        __shared__ float bestA[48], bestB[48];
        __shared__ float pv1[48];
        __shared__ int pi1[48];
        const int b = blockIdx.x - NB;
        const float* tv = g_tagvec + (size_t)b * SL * NT;
        const int t = threadIdx.x;
        const int half = t >> 6;
        const int j = t & 63;
        const bool act = j < 48;
        const int i0 = half * 24;

        float Tc[24];
        if (act) {
#pragma unroll
            for (int r = 0; r < 24; r++) Tc[r] = trans[(i0 + r) * TD + j];
            if (half == 0) bestA[j] = trans[48 * TD + j] + tv[j];  // start + e0
        }
        __syncthreads();

        float en = act ? tv[NT + j] : 0.f;  // prefetched e for s=1
        float* cur = bestA;
        float* nxt = bestB;
        for (int s = 1; s < SL; s++) {
            float mv = -3e38f;
            int mi = i0;
            if (act) {
                float e = en;
                int sn = (s + 1 < SL) ? (s + 1) : s;
                en = tv[sn * NT + j];  // prefetch next step's emission

                float v[4] = {-3e38f, -3e38f, -3e38f, -3e38f};
                int id[4] = {i0, i0 + 1, i0 + 2, i0 + 3};
#pragma unroll
                for (int r = 0; r < 24; r++) {
                    // reference-exact rounding: (best_prev + T) + e, then max
                    float cand = (cur[i0 + r] + Tc[r]) + e;
                    int c = r & 3;
                    bool g = cand > v[c];  // strict > keeps first index
                    v[c] = g ? cand : v[c];
                    id[c] = g ? (i0 + r) : id[c];
                }
                mv = v[0]; mi = id[0];
                if (v[1] > mv || (v[1] == mv && id[1] < mi)) { mv = v[1]; mi = id[1]; }
                if (v[2] > mv || (v[2] == mv && id[2] < mi)) { mv = v[2]; mi = id[2]; }
                if (v[3] > mv || (v[3] == mv && id[3] < mi)) { mv = v[3]; mi = id[3]; }
                if (half == 1) { pv1[j] = mv; pi1[j] = mi; }
            }
            __syncthreads();
            if (act && half == 0) {
                float v1 = pv1[j];
                if (v1 > mv) { mv = v1; mi = pi1[j]; }  // tie -> half0 (lower i)
                nxt[j] = mv;                             // e already included
                idxS[s * NT + j] = (unsigned char)mi;
            }
            __syncthreads();
            float* tmp = cur; cur = nxt; nxt = tmp;
        }

        if (t == 0) {
            float bv = -3e38f;
            int now = 0;
#pragma unroll
            for (int jj = 0; jj < 48; jj++) {
                float f = cur[jj] + trans[jj * TD + 49];
                if (f > bv) { bv = f; now = jj; }
            }
            int off = (out_size >= NB + NB * SL) ? NB : 0;
            float* po = out + off + (size_t)b * SL;
            po[SL - 1] = (float)now;
            for (int s = SL - 1; s >= 1; s--) {
                now = idxS[s * NT + now];
                po[s - 1] = (float)now;
            }
        }
    }
}

extern "C" void kernel_launch(void* const* d_in, const int* in_sizes, int n_in,
                              void* d_out, int out_size) {
    const float* feat  = (const float*)d_in[0];   // [64,1024,512] f32
    const int*   y     = (const int*)d_in[1];     // [64,1024] i32
    const float* W     = (const float*)d_in[3];   // [48,512] f32
    const float* trans = (const float*)d_in[4];   // [50,50] f32
    float* out = (float*)d_out;

    cudaFuncSetAttribute(scan_kernel, cudaFuncAttributeMaxDynamicSharedMemorySize,
                         SL * NT + 1024);

    gemm_kernel<<<512, 128>>>(feat, W);
    scan_kernel<<<2 * NB, 128, SL * NT>>>(y, trans, out, out_size);
}